// round 1
// baseline (speedup 1.0000x reference)
#include <cuda_runtime.h>
#include <math.h>
#include <stdint.h>

// Problem dims
constexpr int Bb = 128, Ss = 64, Ee = 256, Hh = 256, Dd = 256, Aa = 256, Vv = 10000;

// ---------------- scratch (single __device__ global; no allocation) -------
constexpr size_t OFF_EMB   = 0;
constexpr size_t OFF_XPF   = OFF_EMB   + (size_t)Bb*Ss*Ee;        // [B*S, 3H]
constexpr size_t OFF_XPB   = OFF_XPF   + (size_t)Bb*Ss*3*Hh;
constexpr size_t OFF_ENCO  = OFF_XPB   + (size_t)Bb*Ss*3*Hh;      // [B*S, 2H]
constexpr size_t OFF_ENCP  = OFF_ENCO  + (size_t)Bb*Ss*2*Hh;      // [B*S, A]
constexpr size_t OFF_HF    = OFF_ENCP  + (size_t)Bb*Ss*Aa;
constexpr size_t OFF_HB    = OFF_HF    + (size_t)Bb*Hh;
constexpr size_t OFF_HID   = OFF_HB    + (size_t)Bb*Hh;
constexpr size_t OFF_FCIN  = OFF_HID   + (size_t)Bb*Dd;
constexpr size_t OFF_HP1   = OFF_FCIN  + (size_t)Bb*2*Hh;         // hp forward / dec
constexpr size_t OFF_HP2   = OFF_HP1   + (size_t)Bb*3*Hh;         // hp backward
constexpr size_t OFF_HPROJ = OFF_HP2   + (size_t)Bb*3*Hh;
constexpr size_t OFF_RNIN  = OFF_HPROJ + (size_t)Bb*Aa;           // [B, E+2H]
constexpr size_t OFF_CAT   = OFF_RNIN  + (size_t)Bb*(Ee+2*Hh);    // [B, D+2H+E]
constexpr size_t OFF_XPD   = OFF_CAT   + (size_t)Bb*(Dd+2*Hh+Ee); // [B, 3D]
constexpr size_t OFF_TOK   = OFF_XPD   + (size_t)Bb*3*Dd;         // int tokens
constexpr size_t SCR_TOTAL = OFF_TOK   + (size_t)Bb;

__device__ float g_scratch[SCR_TOTAL];

__device__ __forceinline__ float sigf(float x) { return 1.f / (1.f + expf(-x)); }

// ---------------- generic NT GEMM: C = A[M,K] @ B[N,K]^T + bias ----------
template<int BM, int BN, int BK, int TM, int TN, int ACT>
__global__ void gemm_nt(const float* __restrict__ A, int lda,
                        const float* __restrict__ Bm, int ldb,
                        float* __restrict__ C, int ldc,
                        const float* __restrict__ bias,
                        int M, int N, int K)
{
    constexpr int TX = BN / TN, TY = BM / TM;           // TX*TY == 256
    __shared__ float sA[BK][BM];
    __shared__ float sB[BK][BN];
    const int tid = threadIdx.x;
    const int tx  = tid % TX, ty = tid / TX;
    const int row0 = blockIdx.y * BM, col0 = blockIdx.x * BN;

    float acc[TM][TN];
    #pragma unroll
    for (int i = 0; i < TM; i++)
        #pragma unroll
        for (int j = 0; j < TN; j++) acc[i][j] = 0.f;

    for (int k0 = 0; k0 < K; k0 += BK) {
        #pragma unroll
        for (int i = tid; i < BM * BK; i += TX * TY) {
            int m = i / BK, kk = i % BK;
            int gm = row0 + m;
            sA[kk][m] = (gm < M) ? A[(size_t)gm * lda + k0 + kk] : 0.f;
        }
        #pragma unroll
        for (int i = tid; i < BN * BK; i += TX * TY) {
            int n = i / BK, kk = i % BK;
            int gn = col0 + n;
            sB[kk][n] = (gn < N) ? Bm[(size_t)gn * ldb + k0 + kk] : 0.f;
        }
        __syncthreads();
        #pragma unroll
        for (int kk = 0; kk < BK; kk++) {
            float a[TM], b[TN];
            #pragma unroll
            for (int i = 0; i < TM; i++) a[i] = sA[kk][ty * TM + i];
            #pragma unroll
            for (int j = 0; j < TN; j++) b[j] = sB[kk][tx * TN + j];
            #pragma unroll
            for (int i = 0; i < TM; i++)
                #pragma unroll
                for (int j = 0; j < TN; j++) acc[i][j] += a[i] * b[j];
        }
        __syncthreads();
    }

    #pragma unroll
    for (int i = 0; i < TM; i++) {
        int gm = row0 + ty * TM + i;
        if (gm >= M) continue;
        #pragma unroll
        for (int j = 0; j < TN; j++) {
            int gn = col0 + tx * TN + j;
            if (gn >= N) continue;
            float v = acc[i][j] + (bias ? bias[gn] : 0.f);
            if (ACT == 1) v = tanhf(v);
            C[(size_t)gm * ldc + gn] = v;
        }
    }
}

// ---------------- small helper kernels ------------------------------------
__global__ void init0_kernel(float* hf, float* hb, int* tok)
{
    int i = blockIdx.x * 256 + threadIdx.x;
    if (i < Bb * Hh) { hf[i] = 0.f; hb[i] = 0.f; }
    if (i < Bb) tok[i] = 0;
}

__global__ void embed_kernel(const int* __restrict__ inp,
                             const float* __restrict__ tab,
                             float* __restrict__ emb)
{
    int bs = blockIdx.x, j = threadIdx.x;
    int tk = inp[bs * 2 + 0];
    float m = (float)inp[bs * 2 + 1];
    emb[(size_t)bs * Ee + j] = tab[(size_t)tk * Ee + j] * m;
}

// One encoder GRU step for both directions (grid = (B, 2))
__global__ void enc_gate_kernel(const float* __restrict__ xpf,
                                const float* __restrict__ xpb,
                                const float* __restrict__ hpf,
                                const float* __restrict__ hpb,
                                float* __restrict__ hf, float* __restrict__ hb,
                                float* __restrict__ enc_out, int t)
{
    int b = blockIdx.x, dir = blockIdx.y, j = threadIdx.x;
    const float* xp; const float* hp; float* h; int s, col;
    if (dir == 0) { s = t;          xp = xpf + ((size_t)b*Ss + s)*(3*Hh); hp = hpf + (size_t)b*3*Hh; h = hf + (size_t)b*Hh; col = 0;  }
    else          { s = Ss - 1 - t; xp = xpb + ((size_t)b*Ss + s)*(3*Hh); hp = hpb + (size_t)b*3*Hh; h = hb + (size_t)b*Hh; col = Hh; }
    float r = sigf(xp[j]        + hp[j]);
    float z = sigf(xp[Hh + j]   + hp[Hh + j]);
    float n = tanhf(xp[2*Hh + j] + r * hp[2*Hh + j]);
    float hv = h[j];
    float hn = (1.f - z) * n + z * hv;
    h[j] = hn;
    enc_out[((size_t)b*Ss + s)*(2*Hh) + col + j] = hn;
}

__global__ void concat_fc_kernel(const float* __restrict__ hf,
                                 const float* __restrict__ hb,
                                 float* __restrict__ fcin)
{
    int b = blockIdx.x, j = threadIdx.x;
    fcin[(size_t)b*2*Hh + j]      = hf[(size_t)b*Hh + j];
    fcin[(size_t)b*2*Hh + Hh + j] = hb[(size_t)b*Hh + j];
}

// attention: energy=tanh(enc_proj + h_proj), a=softmax_s(sum_a energy), w=a@enc_out
__global__ void attn_kernel(const float* __restrict__ encp,
                            const float* __restrict__ hproj,
                            const float* __restrict__ enc_out,
                            float* __restrict__ rnin, float* __restrict__ cat)
{
    int b = blockIdx.x, tid = threadIdx.x;
    int lane = tid & 31, w = tid >> 5;
    __shared__ float shp[Aa];
    __shared__ float salpha[Ss];
    shp[tid] = hproj[(size_t)b*Aa + tid];
    __syncthreads();
    // 8 warps x 8 s-positions each: reduce over A=256
    #pragma unroll
    for (int i = 0; i < 8; i++) {
        int s = w + 8 * i;
        const float* row = encp + ((size_t)b*Ss + s)*Aa;
        float acc = 0.f;
        #pragma unroll
        for (int a = lane; a < Aa; a += 32) acc += tanhf(row[a] + shp[a]);
        #pragma unroll
        for (int o = 16; o; o >>= 1) acc += __shfl_xor_sync(0xffffffffu, acc, o);
        if (lane == 0) salpha[s] = acc;
    }
    __syncthreads();
    if (w == 0) {   // softmax over 64 in warp 0
        float v0 = salpha[lane], v1 = salpha[lane + 32];
        float m = fmaxf(v0, v1);
        #pragma unroll
        for (int o = 16; o; o >>= 1) m = fmaxf(m, __shfl_xor_sync(0xffffffffu, m, o));
        float e0 = expf(v0 - m), e1 = expf(v1 - m);
        float sum = e0 + e1;
        #pragma unroll
        for (int o = 16; o; o >>= 1) sum += __shfl_xor_sync(0xffffffffu, sum, o);
        float inv = 1.f / sum;
        salpha[lane] = e0 * inv; salpha[lane + 32] = e1 * inv;
    }
    __syncthreads();
    float a0 = 0.f, a1 = 0.f;
    for (int s = 0; s < Ss; s++) {
        float al = salpha[s];
        const float* eo = enc_out + ((size_t)b*Ss + s)*(2*Hh);
        a0 += al * eo[tid];
        a1 += al * eo[Hh + tid];
    }
    rnin[(size_t)b*(Ee+2*Hh) + Ee + tid]      = a0;
    rnin[(size_t)b*(Ee+2*Hh) + Ee + Hh + tid] = a1;
    cat[(size_t)b*(Dd+2*Hh+Ee) + Dd + tid]      = a0;
    cat[(size_t)b*(Dd+2*Hh+Ee) + Dd + Hh + tid] = a1;
}

__global__ void embed_dec_kernel(const int* __restrict__ tok,
                                 const float* __restrict__ tab,
                                 float* __restrict__ rnin, float* __restrict__ cat)
{
    int b = blockIdx.x, j = threadIdx.x;
    int tk = tok[b];
    float e = tab[(size_t)tk*Ee + j];
    rnin[(size_t)b*(Ee+2*Hh) + j] = e;
    cat[(size_t)b*(Dd+2*Hh+Ee) + Dd + 2*Hh + j] = e;
}

__global__ void dec_gate_kernel(const float* __restrict__ xp,
                                const float* __restrict__ hp,
                                float* __restrict__ h, float* __restrict__ cat)
{
    int b = blockIdx.x, j = threadIdx.x;
    const float* x = xp + (size_t)b*3*Dd;
    const float* p = hp + (size_t)b*3*Dd;
    float r = sigf(x[j]         + p[j]);
    float z = sigf(x[Dd + j]    + p[Dd + j]);
    float n = tanhf(x[2*Dd + j] + r * p[2*Dd + j]);
    float hv = h[(size_t)b*Dd + j];
    float hn = (1.f - z) * n + z * hv;
    h[(size_t)b*Dd + j] = hn;
    cat[(size_t)b*(Dd+2*Hh+Ee) + j] = hn;
}

__global__ void argmax_kernel(const float* __restrict__ out, int row_off,
                              int* __restrict__ tok)
{
    int b = blockIdx.x, tid = threadIdx.x;
    const float* row = out + ((size_t)b*Ss + row_off)*Vv;
    float bm = -INFINITY; int bi = 0;
    for (int v = tid; v < Vv; v += 256) {
        float x = row[v];
        if (x > bm) { bm = x; bi = v; }
    }
    __shared__ float sv[256];
    __shared__ int   si[256];
    sv[tid] = bm; si[tid] = bi;
    __syncthreads();
    for (int o = 128; o; o >>= 1) {
        if (tid < o) {
            if (sv[tid+o] > sv[tid] || (sv[tid+o] == sv[tid] && si[tid+o] < si[tid])) {
                sv[tid] = sv[tid+o]; si[tid] = si[tid+o];
            }
        }
        __syncthreads();
    }
    if (tid == 0) tok[b] = si[0];
}

__global__ void logsoftmax_kernel(float* __restrict__ out)
{
    int row = blockIdx.x, tid = threadIdx.x;
    int s = row & (Ss - 1);
    float* p = out + (size_t)row * Vv;
    if (s == 0) {
        float L = logf(expf(1.f) + (float)(Vv - 1));
        for (int v = tid; v < Vv; v += 256) p[v] = (v == 0 ? 1.f : 0.f) - L;
        return;
    }
    constexpr int PT = (Vv + 255) / 256;   // 40
    float regs[PT];
    float m = -INFINITY;
    #pragma unroll
    for (int i = 0; i < PT; i++) {
        int v = tid + i * 256;
        if (v < Vv) { regs[i] = p[v]; m = fmaxf(m, regs[i]); }
        else regs[i] = -INFINITY;
    }
    __shared__ float sm[256];
    sm[tid] = m; __syncthreads();
    for (int o = 128; o; o >>= 1) { if (tid < o) sm[tid] = fmaxf(sm[tid], sm[tid+o]); __syncthreads(); }
    m = sm[0]; __syncthreads();
    float sum = 0.f;
    #pragma unroll
    for (int i = 0; i < PT; i++) {
        int v = tid + i * 256;
        if (v < Vv) sum += expf(regs[i] - m);
    }
    sm[tid] = sum; __syncthreads();
    for (int o = 128; o; o >>= 1) { if (tid < o) sm[tid] += sm[tid+o]; __syncthreads(); }
    float ls = m + logf(sm[0]);
    #pragma unroll
    for (int i = 0; i < PT; i++) {
        int v = tid + i * 256;
        if (v < Vv) p[v] = regs[i] - ls;
    }
}

// ---------------- launch helpers ------------------------------------------
static inline dim3 grid_for(int M, int N, int BM, int BN)
{
    return dim3((N + BN - 1) / BN, (M + BM - 1) / BM);
}

#define GEMM_BIG(A, lda, Bm, ldb, C, ldc, bias, M, N, K, ACT)                          \
    gemm_nt<64,64,16,4,4,ACT><<<grid_for(M, N, 64, 64), 256>>>(A, lda, Bm, ldb, C, ldc, bias, M, N, K)
#define GEMM_SMALL(A, lda, Bm, ldb, C, ldc, bias, M, N, K, ACT)                        \
    gemm_nt<32,32,32,2,2,ACT><<<grid_for(M, N, 32, 32), 256>>>(A, lda, Bm, ldb, C, ldc, bias, M, N, K)

extern "C" void kernel_launch(void* const* d_in, const int* in_sizes, int n_in,
                              void* d_out, int out_size)
{
    const int*   inp       = (const int*)  d_in[0];
    const float* emb_table = (const float*)d_in[1];
    const float* Wih_f     = (const float*)d_in[2];
    const float* Whh_f     = (const float*)d_in[3];
    const float* bih_f     = (const float*)d_in[4];
    const float* bhh_f     = (const float*)d_in[5];
    const float* Wih_b     = (const float*)d_in[6];
    const float* Whh_b     = (const float*)d_in[7];
    const float* bih_b     = (const float*)d_in[8];
    const float* bhh_b     = (const float*)d_in[9];
    const float* fc_W      = (const float*)d_in[10];
    const float* fc_b      = (const float*)d_in[11];
    const float* attn_W    = (const float*)d_in[12];
    const float* attn_b    = (const float*)d_in[13];
    const float* dec_Wih   = (const float*)d_in[14];
    const float* dec_Whh   = (const float*)d_in[15];
    const float* dec_bih   = (const float*)d_in[16];
    const float* dec_bhh   = (const float*)d_in[17];
    const float* out_W     = (const float*)d_in[18];
    const float* out_b     = (const float*)d_in[19];
    float* out = (float*)d_out;

    float* scr = nullptr;
    cudaGetSymbolAddress((void**)&scr, g_scratch);
    float* emb   = scr + OFF_EMB;
    float* xpf   = scr + OFF_XPF;
    float* xpb   = scr + OFF_XPB;
    float* enco  = scr + OFF_ENCO;
    float* encp  = scr + OFF_ENCP;
    float* hf    = scr + OFF_HF;
    float* hb    = scr + OFF_HB;
    float* hid   = scr + OFF_HID;
    float* fcin  = scr + OFF_FCIN;
    float* hp1   = scr + OFF_HP1;
    float* hp2   = scr + OFF_HP2;
    float* hproj = scr + OFF_HPROJ;
    float* rnin  = scr + OFF_RNIN;
    float* cat   = scr + OFF_CAT;
    float* xpd   = scr + OFF_XPD;
    int*   tok   = (int*)(scr + OFF_TOK);

    // ---- init + embedding + input projections (one-time GEMMs) ----
    init0_kernel<<<(Bb*Hh + 255)/256, 256>>>(hf, hb, tok);
    embed_kernel<<<Bb*Ss, 256>>>(inp, emb_table, emb);
    GEMM_BIG(emb, Ee, Wih_f, Ee, xpf, 3*Hh, bih_f, Bb*Ss, 3*Hh, Ee, 0);
    GEMM_BIG(emb, Ee, Wih_b, Ee, xpb, 3*Hh, bih_b, Bb*Ss, 3*Hh, Ee, 0);

    // ---- encoder recurrence (fwd + bwd in lockstep) ----
    for (int t = 0; t < Ss; t++) {
        GEMM_SMALL(hf, Hh, Whh_f, Hh, hp1, 3*Hh, bhh_f, Bb, 3*Hh, Hh, 0);
        GEMM_SMALL(hb, Hh, Whh_b, Hh, hp2, 3*Hh, bhh_b, Bb, 3*Hh, Hh, 0);
        enc_gate_kernel<<<dim3(Bb, 2), 256>>>(xpf, xpb, hp1, hp2, hf, hb, enco, t);
    }

    // ---- decoder init: hidden = tanh([f_h, b_h] @ fc_W^T + fc_b) ----
    concat_fc_kernel<<<Bb, 256>>>(hf, hb, fcin);
    GEMM_SMALL(fcin, 2*Hh, fc_W, 2*Hh, hid, Dd, fc_b, Bb, Dd, 2*Hh, 1);

    // ---- precompute attention projection of enc_out (hoisted out of loop) ----
    GEMM_BIG(enco, 2*Hh, attn_W + Dd, (Dd + 2*Hh), encp, Aa, attn_b, Bb*Ss, Aa, 2*Hh, 0);

    // ---- decoder steps ----
    for (int t = 0; t < Ss - 1; t++) {
        GEMM_SMALL(hid, Dd, attn_W, (Dd + 2*Hh), hproj, Aa, (const float*)nullptr, Bb, Aa, Dd, 0);
        attn_kernel<<<Bb, 256>>>(encp, hproj, enco, rnin, cat);
        embed_dec_kernel<<<Bb, 256>>>(tok, emb_table, rnin, cat);
        GEMM_SMALL(rnin, Ee + 2*Hh, dec_Wih, Ee + 2*Hh, xpd, 3*Dd, dec_bih, Bb, 3*Dd, Ee + 2*Hh, 0);
        GEMM_SMALL(hid, Dd, dec_Whh, Dd, hp1, 3*Dd, dec_bhh, Bb, 3*Dd, Dd, 0);
        dec_gate_kernel<<<Bb, 256>>>(xpd, hp1, hid, cat);
        // logits straight into the output buffer at rows (b, t+1)
        GEMM_BIG(cat, Dd + 2*Hh + Ee, out_W, Dd + 2*Hh + Ee,
                 out + (size_t)(t + 1) * Vv, Ss * Vv, out_b,
                 Bb, Vv, Dd + 2*Hh + Ee, 0);
        argmax_kernel<<<Bb, 256>>>(out, t + 1, tok);
    }

    // ---- final log-softmax (rows s==0 are the fixed one-hot rows) ----
    logsoftmax_kernel<<<Bb*Ss, 256>>>(out);
}

// round 2
// speedup vs baseline: 1.5533x; 1.5533x over previous
#include <cuda_runtime.h>
#include <math.h>
#include <stdint.h>

// Problem dims
constexpr int Bb = 128, Ss = 64, Ee = 256, Hh = 256, Dd = 256, Aa = 256, Vv = 10000;

// ---------------- scratch (single __device__ global; no allocation) -------
constexpr size_t OFF_EMB   = 0;
constexpr size_t OFF_XPF   = OFF_EMB   + (size_t)Bb*Ss*Ee;        // [B*S, 3H]
constexpr size_t OFF_XPB   = OFF_XPF   + (size_t)Bb*Ss*3*Hh;
constexpr size_t OFF_ENCO  = OFF_XPB   + (size_t)Bb*Ss*3*Hh;      // [B*S, 2H]
constexpr size_t OFF_ENCP  = OFF_ENCO  + (size_t)Bb*Ss*2*Hh;      // [B*S, A]
constexpr size_t OFF_HF    = OFF_ENCP  + (size_t)Bb*Ss*Aa;
constexpr size_t OFF_HB    = OFF_HF    + (size_t)Bb*Hh;
constexpr size_t OFF_HID   = OFF_HB    + (size_t)Bb*Hh;
constexpr size_t OFF_FCIN  = OFF_HID   + (size_t)Bb*Dd;
constexpr size_t OFF_HP1   = OFF_FCIN  + (size_t)Bb*2*Hh;         // hp forward / dec
constexpr size_t OFF_HP2   = OFF_HP1   + (size_t)Bb*3*Hh;         // hp backward
constexpr size_t OFF_HPROJ = OFF_HP2   + (size_t)Bb*3*Hh;
constexpr size_t OFF_RNIN  = OFF_HPROJ + (size_t)Bb*Aa;           // [B, E+2H]
constexpr size_t OFF_CAT   = OFF_RNIN  + (size_t)Bb*(Ee+2*Hh);    // [B, D+2H+E]
constexpr size_t OFF_XPD   = OFF_CAT   + (size_t)Bb*(Dd+2*Hh+Ee); // [B, 3D]
constexpr size_t OFF_SLOT  = OFF_XPD   + (size_t)Bb*3*Dd;         // 128 u64 = 256 floats
constexpr size_t SCR_TOTAL = OFF_SLOT  + (size_t)2*Bb;

__device__ __align__(256) float g_scratch[SCR_TOTAL];

__device__ __forceinline__ float sigf(float x) { return 1.f / (1.f + expf(-x)); }

// monotonic float -> u32 mapping (preserves ordering, injective)
__device__ __forceinline__ unsigned int fmono(float x) {
    unsigned int b = __float_as_uint(x);
    return (b & 0x80000000u) ? ~b : (b | 0x80000000u);
}

// =====================================================================
//  Fast 64x64 GEMM  C[M,N] = A[M,K] @ B[N,K]^T (+bias)
//  requirements: M%64==0, K%16==0, lda%4==0, ldb%4==0, 16B-aligned bases
//  AMAX: fused per-row argmax into u64 slots (atomicMax)
// =====================================================================
template<int ACT, int AMAX>
__global__ void gemm64(const float* __restrict__ A, int lda,
                       const float* __restrict__ Bm, int ldb,
                       float* __restrict__ C, int ldc,
                       const float* __restrict__ bias,
                       int M, int N, int K,
                       unsigned long long* __restrict__ slots)
{
    __shared__ float sA[16][68];
    __shared__ float sB[16][68];
    const int tid = threadIdx.x;
    const int lr = tid >> 2;         // 0..63 (load row)
    const int lc = tid & 3;          // 0..3  (float4 chunk along K)
    const int tx = tid & 15;         // col group
    const int ty = tid >> 4;         // row group
    const int row0 = blockIdx.y * 64, col0 = blockIdx.x * 64;

    float acc[4][4];
    #pragma unroll
    for (int i = 0; i < 4; i++)
        #pragma unroll
        for (int j = 0; j < 4; j++) acc[i][j] = 0.f;

    const float* Aptr = A + (size_t)(row0 + lr) * lda + 4 * lc;
    const int gnl = col0 + lr;
    const float* Bptr = Bm + (size_t)gnl * ldb + 4 * lc;
    const bool bvalid = (gnl < N);

    for (int k0 = 0; k0 < K; k0 += 16) {
        float4 va = *reinterpret_cast<const float4*>(Aptr + k0);
        float4 vb = make_float4(0.f, 0.f, 0.f, 0.f);
        if (bvalid) vb = *reinterpret_cast<const float4*>(Bptr + k0);
        sA[4*lc+0][lr] = va.x; sA[4*lc+1][lr] = va.y;
        sA[4*lc+2][lr] = va.z; sA[4*lc+3][lr] = va.w;
        sB[4*lc+0][lr] = vb.x; sB[4*lc+1][lr] = vb.y;
        sB[4*lc+2][lr] = vb.z; sB[4*lc+3][lr] = vb.w;
        __syncthreads();
        #pragma unroll
        for (int kk = 0; kk < 16; kk++) {
            float4 a4 = *reinterpret_cast<const float4*>(&sA[kk][ty*4]);
            float4 b4 = *reinterpret_cast<const float4*>(&sB[kk][tx*4]);
            float a[4] = {a4.x, a4.y, a4.z, a4.w};
            float b[4] = {b4.x, b4.y, b4.z, b4.w};
            #pragma unroll
            for (int i = 0; i < 4; i++)
                #pragma unroll
                for (int j = 0; j < 4; j++) acc[i][j] += a[i] * b[j];
        }
        __syncthreads();
    }

    #pragma unroll
    for (int i = 0; i < 4; i++) {
        int gm = row0 + ty*4 + i;
        float bestv = -INFINITY; int besti = 0;
        #pragma unroll
        for (int j = 0; j < 4; j++) {
            int gn = col0 + tx*4 + j;
            if (gn < N) {
                float v = acc[i][j] + (bias ? bias[gn] : 0.f);
                if (ACT == 1) v = tanhf(v);
                C[(size_t)gm * ldc + gn] = v;
                if (AMAX) { if (v > bestv) { bestv = v; besti = gn; } }
            }
        }
        if (AMAX) {
            unsigned long long key =
                ((unsigned long long)fmono(bestv) << 32) |
                (unsigned long long)(0xFFFFFFFFu - (unsigned)besti);
            #pragma unroll
            for (int o = 8; o; o >>= 1) {
                unsigned long long ok = __shfl_xor_sync(0xffffffffu, key, o);
                if (ok > key) key = ok;
            }
            if (tx == 0) atomicMax(&slots[gm], key);
        }
    }
}

// ---------------- generic small GEMM tile (device fn) ---------------------
template<int BM, int BN, int BK, int TM, int TN>
__device__ __forceinline__ void gemm_tile(const float* __restrict__ A, int lda,
                                          const float* __restrict__ Bm, int ldb,
                                          float* __restrict__ C, int ldc,
                                          const float* __restrict__ bias,
                                          int M, int N, int K,
                                          int row0, int col0, int ACT)
{
    constexpr int TX = BN / TN, TY = BM / TM;
    __shared__ float sA[BK][BM];
    __shared__ float sB[BK][BN];
    const int tid = threadIdx.x;
    const int tx = tid % TX, ty = tid / TX;

    float acc[TM][TN];
    #pragma unroll
    for (int i = 0; i < TM; i++)
        #pragma unroll
        for (int j = 0; j < TN; j++) acc[i][j] = 0.f;

    for (int k0 = 0; k0 < K; k0 += BK) {
        #pragma unroll
        for (int i = tid; i < BM * BK; i += TX * TY) {
            int m = i / BK, kk = i % BK;
            int gm = row0 + m;
            sA[kk][m] = (gm < M) ? A[(size_t)gm * lda + k0 + kk] : 0.f;
        }
        #pragma unroll
        for (int i = tid; i < BN * BK; i += TX * TY) {
            int n = i / BK, kk = i % BK;
            int gn = col0 + n;
            sB[kk][n] = (gn < N) ? Bm[(size_t)gn * ldb + k0 + kk] : 0.f;
        }
        __syncthreads();
        #pragma unroll
        for (int kk = 0; kk < BK; kk++) {
            float a[TM], b[TN];
            #pragma unroll
            for (int i = 0; i < TM; i++) a[i] = sA[kk][ty * TM + i];
            #pragma unroll
            for (int j = 0; j < TN; j++) b[j] = sB[kk][tx * TN + j];
            #pragma unroll
            for (int i = 0; i < TM; i++)
                #pragma unroll
                for (int j = 0; j < TN; j++) acc[i][j] += a[i] * b[j];
        }
        __syncthreads();
    }

    #pragma unroll
    for (int i = 0; i < TM; i++) {
        int gm = row0 + ty * TM + i;
        if (gm >= M) continue;
        #pragma unroll
        for (int j = 0; j < TN; j++) {
            int gn = col0 + tx * TN + j;
            if (gn >= N) continue;
            float v = acc[i][j] + (bias ? bias[gn] : 0.f);
            if (ACT == 1) v = tanhf(v);
            C[(size_t)gm * ldc + gn] = v;
        }
    }
}

template<int ACT>
__global__ void gemm32(const float* __restrict__ A, int lda,
                       const float* __restrict__ Bm, int ldb,
                       float* __restrict__ C, int ldc,
                       const float* __restrict__ bias,
                       int M, int N, int K)
{
    gemm_tile<32,32,32,2,2>(A, lda, Bm, ldb, C, ldc, bias, M, N, K,
                            blockIdx.y * 32, blockIdx.x * 32, ACT);
}

// Encoder: both directions' recurrent GEMM in one launch (z = dir)
__global__ void enc_gemm_kernel(const float* __restrict__ hf, const float* __restrict__ hb,
                                const float* __restrict__ Whh_f, const float* __restrict__ Whh_b,
                                const float* __restrict__ bhh_f, const float* __restrict__ bhh_b,
                                float* __restrict__ hp1, float* __restrict__ hp2)
{
    int dir = blockIdx.z;
    gemm_tile<32,32,32,2,2>(dir ? hb : hf, Hh,
                            dir ? Whh_b : Whh_f, Hh,
                            dir ? hp2 : hp1, 3*Hh,
                            dir ? bhh_b : bhh_f,
                            Bb, 3*Hh, Hh, blockIdx.y * 32, blockIdx.x * 32, 0);
}

// Decoder: hproj = hid @ attn_W[:, :D]^T  AND  hp1 = hid @ dec_Whh^T + bhh, one launch
__global__ void dec_dual_gemm(const float* __restrict__ hid,
                              const float* __restrict__ attn_W,
                              const float* __restrict__ dec_Whh,
                              const float* __restrict__ dec_bhh,
                              float* __restrict__ hproj, float* __restrict__ hp1)
{
    int col0 = blockIdx.x * 32;
    if (col0 < Aa) {
        gemm_tile<32,32,32,2,2>(hid, Dd, attn_W, Dd + 2*Hh, hproj, Aa,
                                (const float*)nullptr, Bb, Aa, Dd,
                                blockIdx.y * 32, col0, 0);
    } else {
        gemm_tile<32,32,32,2,2>(hid, Dd, dec_Whh, Dd, hp1, 3*Dd,
                                dec_bhh, Bb, 3*Dd, Dd,
                                blockIdx.y * 32, col0 - Aa, 0);
    }
}

// ---------------- small helper kernels ------------------------------------
__global__ void init0_kernel(float* hf, float* hb, unsigned long long* slots)
{
    int i = blockIdx.x * 256 + threadIdx.x;
    if (i < Bb * Hh) { hf[i] = 0.f; hb[i] = 0.f; }
    if (i < Bb)
        slots[i] = ((unsigned long long)fmono(0.f) << 32) | 0xFFFFFFFFull; // idx 0
}

__global__ void embed_kernel(const int* __restrict__ inp,
                             const float* __restrict__ tab,
                             float* __restrict__ emb)
{
    int bs = blockIdx.x, j = threadIdx.x;
    int tk = inp[bs * 2 + 0];
    float m = (float)inp[bs * 2 + 1];
    emb[(size_t)bs * Ee + j] = tab[(size_t)tk * Ee + j] * m;
}

__global__ void enc_gate_kernel(const float* __restrict__ xpf,
                                const float* __restrict__ xpb,
                                const float* __restrict__ hpf,
                                const float* __restrict__ hpb,
                                float* __restrict__ hf, float* __restrict__ hb,
                                float* __restrict__ enc_out, int t)
{
    int b = blockIdx.x, dir = blockIdx.y, j = threadIdx.x;
    const float* xp; const float* hp; float* h; int s, col;
    if (dir == 0) { s = t;          xp = xpf + ((size_t)b*Ss + s)*(3*Hh); hp = hpf + (size_t)b*3*Hh; h = hf + (size_t)b*Hh; col = 0;  }
    else          { s = Ss - 1 - t; xp = xpb + ((size_t)b*Ss + s)*(3*Hh); hp = hpb + (size_t)b*3*Hh; h = hb + (size_t)b*Hh; col = Hh; }
    float r = sigf(xp[j]        + hp[j]);
    float z = sigf(xp[Hh + j]   + hp[Hh + j]);
    float n = tanhf(xp[2*Hh + j] + r * hp[2*Hh + j]);
    float hv = h[j];
    float hn = (1.f - z) * n + z * hv;
    h[j] = hn;
    enc_out[((size_t)b*Ss + s)*(2*Hh) + col + j] = hn;
}

__global__ void concat_fc_kernel(const float* __restrict__ hf,
                                 const float* __restrict__ hb,
                                 float* __restrict__ fcin)
{
    int b = blockIdx.x, j = threadIdx.x;
    fcin[(size_t)b*2*Hh + j]      = hf[(size_t)b*Hh + j];
    fcin[(size_t)b*2*Hh + Hh + j] = hb[(size_t)b*Hh + j];
}

// attention + decoder-token embedding in one kernel
__global__ void attn_embed_kernel(const float* __restrict__ encp,
                                  const float* __restrict__ hproj,
                                  const float* __restrict__ enc_out,
                                  const unsigned long long* __restrict__ slots,
                                  const float* __restrict__ tab,
                                  float* __restrict__ rnin, float* __restrict__ cat)
{
    int b = blockIdx.x, tid = threadIdx.x;
    int lane = tid & 31, w = tid >> 5;
    __shared__ float shp[Aa];
    __shared__ float salpha[Ss];
    shp[tid] = hproj[(size_t)b*Aa + tid];
    __syncthreads();
    #pragma unroll
    for (int i = 0; i < 8; i++) {
        int s = w + 8 * i;
        const float* row = encp + ((size_t)b*Ss + s)*Aa;
        float acc = 0.f;
        #pragma unroll
        for (int a = lane; a < Aa; a += 32) acc += tanhf(row[a] + shp[a]);
        #pragma unroll
        for (int o = 16; o; o >>= 1) acc += __shfl_xor_sync(0xffffffffu, acc, o);
        if (lane == 0) salpha[s] = acc;
    }
    __syncthreads();
    if (w == 0) {
        float v0 = salpha[lane], v1 = salpha[lane + 32];
        float m = fmaxf(v0, v1);
        #pragma unroll
        for (int o = 16; o; o >>= 1) m = fmaxf(m, __shfl_xor_sync(0xffffffffu, m, o));
        float e0 = expf(v0 - m), e1 = expf(v1 - m);
        float sum = e0 + e1;
        #pragma unroll
        for (int o = 16; o; o >>= 1) sum += __shfl_xor_sync(0xffffffffu, sum, o);
        float inv = 1.f / sum;
        salpha[lane] = e0 * inv; salpha[lane + 32] = e1 * inv;
    }
    __syncthreads();
    float a0 = 0.f, a1 = 0.f;
    for (int s = 0; s < Ss; s++) {
        float al = salpha[s];
        const float* eo = enc_out + ((size_t)b*Ss + s)*(2*Hh);
        a0 += al * eo[tid];
        a1 += al * eo[Hh + tid];
    }
    rnin[(size_t)b*(Ee+2*Hh) + Ee + tid]      = a0;
    rnin[(size_t)b*(Ee+2*Hh) + Ee + Hh + tid] = a1;
    cat[(size_t)b*(Dd+2*Hh+Ee) + Dd + tid]      = a0;
    cat[(size_t)b*(Dd+2*Hh+Ee) + Dd + Hh + tid] = a1;

    // token embedding (decoded from packed argmax slot)
    int tk = (int)(0xFFFFFFFFu - (unsigned)(slots[b] & 0xFFFFFFFFull));
    float e = tab[(size_t)tk * Ee + tid];
    rnin[(size_t)b*(Ee+2*Hh) + tid] = e;
    cat[(size_t)b*(Dd+2*Hh+Ee) + Dd + 2*Hh + tid] = e;
}

__global__ void dec_gate_kernel(const float* __restrict__ xp,
                                const float* __restrict__ hp,
                                float* __restrict__ h, float* __restrict__ cat,
                                unsigned long long* __restrict__ slots)
{
    int b = blockIdx.x, j = threadIdx.x;
    const float* x = xp + (size_t)b*3*Dd;
    const float* p = hp + (size_t)b*3*Dd;
    float r = sigf(x[j]         + p[j]);
    float z = sigf(x[Dd + j]    + p[Dd + j]);
    float n = tanhf(x[2*Dd + j] + r * p[2*Dd + j]);
    float hv = h[(size_t)b*Dd + j];
    float hn = (1.f - z) * n + z * hv;
    h[(size_t)b*Dd + j] = hn;
    cat[(size_t)b*(Dd+2*Hh+Ee) + j] = hn;
    if (j == 0) slots[b] = 0ull;   // reset argmax slot before logits GEMM
}

__global__ void logsoftmax_kernel(float* __restrict__ out)
{
    int row = blockIdx.x, tid = threadIdx.x;
    int s = row & (Ss - 1);
    float* p = out + (size_t)row * Vv;
    if (s == 0) {
        float L = logf(expf(1.f) + (float)(Vv - 1));
        for (int v = tid; v < Vv; v += 256) p[v] = (v == 0 ? 1.f : 0.f) - L;
        return;
    }
    constexpr int PT = (Vv + 255) / 256;
    float regs[PT];
    float m = -INFINITY;
    #pragma unroll
    for (int i = 0; i < PT; i++) {
        int v = tid + i * 256;
        if (v < Vv) { regs[i] = p[v]; m = fmaxf(m, regs[i]); }
        else regs[i] = -INFINITY;
    }
    __shared__ float sm[256];
    sm[tid] = m; __syncthreads();
    for (int o = 128; o; o >>= 1) { if (tid < o) sm[tid] = fmaxf(sm[tid], sm[tid+o]); __syncthreads(); }
    m = sm[0]; __syncthreads();
    float sum = 0.f;
    #pragma unroll
    for (int i = 0; i < PT; i++) {
        int v = tid + i * 256;
        if (v < Vv) sum += expf(regs[i] - m);
    }
    sm[tid] = sum; __syncthreads();
    for (int o = 128; o; o >>= 1) { if (tid < o) sm[tid] += sm[tid+o]; __syncthreads(); }
    float ls = m + logf(sm[0]);
    #pragma unroll
    for (int i = 0; i < PT; i++) {
        int v = tid + i * 256;
        if (v < Vv) p[v] = regs[i] - ls;
    }
}

// ---------------- launch helpers ------------------------------------------
static inline dim3 grid64(int M, int N) { return dim3((N + 63) / 64, M / 64); }
static inline dim3 grid32(int M, int N) { return dim3((N + 31) / 32, (M + 31) / 32); }

extern "C" void kernel_launch(void* const* d_in, const int* in_sizes, int n_in,
                              void* d_out, int out_size)
{
    const int*   inp       = (const int*)  d_in[0];
    const float* emb_table = (const float*)d_in[1];
    const float* Wih_f     = (const float*)d_in[2];
    const float* Whh_f     = (const float*)d_in[3];
    const float* bih_f     = (const float*)d_in[4];
    const float* bhh_f     = (const float*)d_in[5];
    const float* Wih_b     = (const float*)d_in[6];
    const float* Whh_b     = (const float*)d_in[7];
    const float* bih_b     = (const float*)d_in[8];
    const float* bhh_b     = (const float*)d_in[9];
    const float* fc_W      = (const float*)d_in[10];
    const float* fc_b      = (const float*)d_in[11];
    const float* attn_W    = (const float*)d_in[12];
    const float* attn_b    = (const float*)d_in[13];
    const float* dec_Wih   = (const float*)d_in[14];
    const float* dec_Whh   = (const float*)d_in[15];
    const float* dec_bih   = (const float*)d_in[16];
    const float* dec_bhh   = (const float*)d_in[17];
    const float* out_W     = (const float*)d_in[18];
    const float* out_b     = (const float*)d_in[19];
    float* out = (float*)d_out;

    float* scr = nullptr;
    cudaGetSymbolAddress((void**)&scr, g_scratch);
    float* emb   = scr + OFF_EMB;
    float* xpf   = scr + OFF_XPF;
    float* xpb   = scr + OFF_XPB;
    float* enco  = scr + OFF_ENCO;
    float* encp  = scr + OFF_ENCP;
    float* hf    = scr + OFF_HF;
    float* hb    = scr + OFF_HB;
    float* hid   = scr + OFF_HID;
    float* fcin  = scr + OFF_FCIN;
    float* hp1   = scr + OFF_HP1;
    float* hp2   = scr + OFF_HP2;
    float* hproj = scr + OFF_HPROJ;
    float* rnin  = scr + OFF_RNIN;
    float* cat   = scr + OFF_CAT;
    float* xpd   = scr + OFF_XPD;
    unsigned long long* slots = (unsigned long long*)(scr + OFF_SLOT);

    // ---- init + embedding + one-time GEMMs (fast 64x64 kernel) ----
    init0_kernel<<<(Bb*Hh + 255)/256, 256>>>(hf, hb, slots);
    embed_kernel<<<Bb*Ss, 256>>>(inp, emb_table, emb);
    gemm64<0,0><<<grid64(Bb*Ss, 3*Hh), 256>>>(emb, Ee, Wih_f, Ee, xpf, 3*Hh, bih_f, Bb*Ss, 3*Hh, Ee, nullptr);
    gemm64<0,0><<<grid64(Bb*Ss, 3*Hh), 256>>>(emb, Ee, Wih_b, Ee, xpb, 3*Hh, bih_b, Bb*Ss, 3*Hh, Ee, nullptr);

    // ---- encoder recurrence (fwd + bwd fused per launch) ----
    for (int t = 0; t < Ss; t++) {
        enc_gemm_kernel<<<dim3(24, 4, 2), 256>>>(hf, hb, Whh_f, Whh_b, bhh_f, bhh_b, hp1, hp2);
        enc_gate_kernel<<<dim3(Bb, 2), 256>>>(xpf, xpb, hp1, hp2, hf, hb, enco, t);
    }

    // ---- decoder init ----
    concat_fc_kernel<<<Bb, 256>>>(hf, hb, fcin);
    gemm32<1><<<grid32(Bb, Dd), 256>>>(fcin, 2*Hh, fc_W, 2*Hh, hid, Dd, fc_b, Bb, Dd, 2*Hh);

    // ---- precompute attention projection of enc_out ----
    gemm64<0,0><<<grid64(Bb*Ss, Aa), 256>>>(enco, 2*Hh, attn_W + Dd, Dd + 2*Hh, encp, Aa, attn_b, Bb*Ss, Aa, 2*Hh, nullptr);

    // ---- decoder steps (5 launches each) ----
    for (int t = 0; t < Ss - 1; t++) {
        dec_dual_gemm<<<dim3((Aa + 3*Dd)/32, Bb/32), 256>>>(hid, attn_W, dec_Whh, dec_bhh, hproj, hp1);
        attn_embed_kernel<<<Bb, 256>>>(encp, hproj, enco, slots, emb_table, rnin, cat);
        gemm32<0><<<grid32(Bb, 3*Dd), 256>>>(rnin, Ee + 2*Hh, dec_Wih, Ee + 2*Hh, xpd, 3*Dd, dec_bih, Bb, 3*Dd, Ee + 2*Hh);
        dec_gate_kernel<<<Bb, 256>>>(xpd, hp1, hid, cat, slots);
        gemm64<0,1><<<grid64(Bb, Vv), 256>>>(cat, Dd + 2*Hh + Ee, out_W, Dd + 2*Hh + Ee,
                                             out + (size_t)(t + 1) * Vv, Ss * Vv, out_b,
                                             Bb, Vv, Dd + 2*Hh + Ee, slots);
    }

    // ---- final log-softmax ----
    logsoftmax_kernel<<<Bb*Ss, 256>>>(out);
}